// round 14
// baseline (speedup 1.0000x reference)
#include <cuda_runtime.h>
#include <cuda_bf16.h>
#include <cstdint>

#define NN 50000
#define EE 800000
#define NG 64
#define FD 128
#define QD 768
#define OD 32

// ---------------- scratch (no allocations allowed) ----------------
__device__ float g_dinv[NN];
__device__ float g_hs  [(size_t)NN * FD];
__device__ float g_h2  [(size_t)NN * FD];
__device__ float g_q [NG * FD];
__device__ float g_qc[NG * FD];
__device__ int   g_cnt[NN];
__device__ int   g_off[NN + 1];
__device__ int   g_cur[NN];
__device__ int   g_csr[EE];
// bf16 weight tiles, [n][k] row-major (col-major B operand): 4 matrices x (hi,lo)
__device__ __nv_bfloat16 g_wBhi[4 * FD * FD];
__device__ __nv_bfloat16 g_wBlo[4 * FD * FD];

__device__ __forceinline__ uint32_t smem_u32(const void* p) {
    uint32_t a;
    asm("{ .reg .u64 t; cvta.to.shared.u64 t, %1; cvt.u32.u64 %0, t; }" : "=r"(a) : "l"(p));
    return a;
}
__device__ __forceinline__ void ldsm_x4(uint32_t* r, uint32_t addr) {
    asm volatile("ldmatrix.sync.aligned.m8n8.x4.shared.b16 {%0,%1,%2,%3}, [%4];"
                 : "=r"(r[0]), "=r"(r[1]), "=r"(r[2]), "=r"(r[3]) : "r"(addr));
}
__device__ __forceinline__ void mma16816(float* c, const uint32_t* a, const uint32_t* b) {
    asm volatile(
        "mma.sync.aligned.m16n8k16.row.col.f32.bf16.bf16.f32 "
        "{%0,%1,%2,%3}, {%4,%5,%6,%7}, {%8,%9}, {%0,%1,%2,%3};"
        : "+f"(c[0]), "+f"(c[1]), "+f"(c[2]), "+f"(c[3])
        : "r"(a[0]), "r"(a[1]), "r"(a[2]), "r"(a[3]), "r"(b[0]), "r"(b[1]));
}

// ---------------- CSR build ----------------
__global__ void k_count(const int* __restrict__ dst) {
    int i = blockIdx.x * blockDim.x + threadIdx.x;
    int stride = gridDim.x * blockDim.x;
    for (; i < EE; i += stride) atomicAdd(&g_cnt[dst[i]], 1);
}
__global__ void __launch_bounds__(1024) k_scan() {
    __shared__ int ps[1024];
    const int t = threadIdx.x;
    const int CH = (NN + 1023) / 1024;
    int b = t * CH, e = b + CH; if (e > NN) e = NN;
    int s = 0;
    for (int i = b; i < e; i++) s += g_cnt[i];
    ps[t] = s;
    __syncthreads();
    for (int d = 1; d < 1024; d <<= 1) {
        int v = (t >= d) ? ps[t - d] : 0;
        __syncthreads();
        ps[t] += v;
        __syncthreads();
    }
    int run = (t > 0) ? ps[t - 1] : 0;
    for (int i = b; i < e; i++) {
        g_off[i] = run;
        g_cur[i] = run;
        g_dinv[i] = rsqrtf((float)(g_cnt[i] + 1));
        run += g_cnt[i];
    }
    if (t == 1023) g_off[NN] = run;
}
__global__ void k_place(const int* __restrict__ src, const int* __restrict__ dst) {
    int i = blockIdx.x * blockDim.x + threadIdx.x;
    int stride = gridDim.x * blockDim.x;
    for (; i < EE; i += stride) {
        int d = dst[i];
        int p = atomicAdd(&g_cur[d], 1);
        g_csr[p] = src[i];
    }
}

// ---------------- weight prep: W[k][n] fp32 -> B[n][k] split bf16 ----------------
__global__ void k_prep(const float* __restrict__ W0, const float* __restrict__ W1,
                       const float* __restrict__ W2, const float* __restrict__ F1)
{
    const float* Ws[4] = {W0, W1, W2, F1};
    int mat = blockIdx.y;
    const float* W = Ws[mat];
    __nv_bfloat16* bh = g_wBhi + mat * FD * FD;
    __nv_bfloat16* bl = g_wBlo + mat * FD * FD;
    for (int idx = blockIdx.x * blockDim.x + threadIdx.x; idx < FD * FD;
         idx += gridDim.x * blockDim.x) {
        int k = idx >> 7, n = idx & 127;
        float v = W[idx];
        __nv_bfloat16 hi = __float2bfloat16_rn(v);
        __nv_bfloat16 lo = __float2bfloat16_rn(v - __bfloat162float(hi));
        bh[n * FD + k] = hi;
        bl[n * FD + k] = lo;
    }
}

// ---------------- tensor-core GEMM: [64-row tile] x [128,128], split-bf16 3-term ----------------
// 256 threads, 8 warps in 2(m) x 4(n) grid, warp tile 32x32. 2 CTAs/SM.
// MODE 0: plain A load; epilogue acc*dinv
// MODE 1: A load = relu(dinv*a + bias_in); epilogue acc*dinv
// MODE 2: A load = relu(dinv*a + bias_in); epilogue relu(acc + qc[batch[row]])
#define SP 136   // padded smem row stride in bf16 elems (272B: odd 16B units -> ldsm conflict-free)
#define MT 64    // M tile rows
template<int MODE>
__global__ void __launch_bounds__(256, 2)
k_mma(const float* __restrict__ A, const float* __restrict__ bias_in,
      const __nv_bfloat16* __restrict__ Bhi, const __nv_bfloat16* __restrict__ Blo,
      float* __restrict__ out0,
      const float* __restrict__ qc, const int* __restrict__ batch, int M)
{
    extern __shared__ __align__(16) __nv_bfloat16 sm[];
    __nv_bfloat16* Ah = sm;                       // 64 x SP
    __nv_bfloat16* Al = sm + MT * SP;             // 64 x SP
    __nv_bfloat16* Bh = sm + 2 * MT * SP;         // 128 x SP
    __nv_bfloat16* Bl = sm + 2 * MT * SP + 128 * SP;

    const int tid = threadIdx.x;
    const int wid = tid >> 5;
    const int lane = tid & 31;
    const int rowBase = blockIdx.x << 6;

    // copy B tiles (16384 bf16 each)
    for (int i = tid; i < 2048; i += 256) {
        int n = i >> 4;
        int k = (i & 15) << 3;
        uint4 vh = ((const uint4*)Bhi)[i];
        uint4 vl = ((const uint4*)Blo)[i];
        *(uint4*)&Bh[n * SP + k] = vh;
        *(uint4*)&Bl[n * SP + k] = vl;
    }
    // load (+optional transform) + split A : 64 rows x 32 float4
    for (int f = tid; f < 2048; f += 256) {
        int row = f >> 5;
        int col = (f & 31) << 2;
        int r = rowBase + row;
        float4 v = make_float4(0.f, 0.f, 0.f, 0.f);
        if (r < M) v = *(const float4*)(A + (size_t)r * FD + col);
        if (MODE != 0) {
            float dv = (r < M) ? g_dinv[r] : 0.f;
            float4 bb = *(const float4*)(bias_in + col);
            v.x = fmaxf(fmaf(dv, v.x, bb.x), 0.f);
            v.y = fmaxf(fmaf(dv, v.y, bb.y), 0.f);
            v.z = fmaxf(fmaf(dv, v.z, bb.z), 0.f);
            v.w = fmaxf(fmaf(dv, v.w, bb.w), 0.f);
        }
        __nv_bfloat16 hx = __float2bfloat16_rn(v.x);
        __nv_bfloat16 hy = __float2bfloat16_rn(v.y);
        __nv_bfloat16 hz = __float2bfloat16_rn(v.z);
        __nv_bfloat16 hw = __float2bfloat16_rn(v.w);
        __nv_bfloat162 h01, h23, l01, l23;
        h01.x = hx; h01.y = hy; h23.x = hz; h23.y = hw;
        l01.x = __float2bfloat16_rn(v.x - __bfloat162float(hx));
        l01.y = __float2bfloat16_rn(v.y - __bfloat162float(hy));
        l23.x = __float2bfloat16_rn(v.z - __bfloat162float(hz));
        l23.y = __float2bfloat16_rn(v.w - __bfloat162float(hw));
        uint2 hv, lv;
        hv.x = *(uint32_t*)&h01; hv.y = *(uint32_t*)&h23;
        lv.x = *(uint32_t*)&l01; lv.y = *(uint32_t*)&l23;
        *(uint2*)&Ah[row * SP + col] = hv;
        *(uint2*)&Al[row * SP + col] = lv;
    }
    __syncthreads();

    const int warp_m = wid & 1;       // rows 32*warp_m
    const int warp_n = wid >> 1;      // cols 32*warp_n

    float acc[2][4][4];
    #pragma unroll
    for (int i = 0; i < 2; i++)
        #pragma unroll
        for (int j = 0; j < 4; j++)
            #pragma unroll
            for (int q = 0; q < 4; q++) acc[i][j][q] = 0.f;

    const uint32_t sAh = smem_u32(Ah);
    const uint32_t sAl = smem_u32(Al);
    const uint32_t sBh = smem_u32(Bh);
    const uint32_t sBl = smem_u32(Bl);

    const int a_row = warp_m * 32 + (lane & 15);
    const int a_kof = (lane >> 4) << 3;
    const int b_n   = warp_n * 32 + (lane & 7) + (((lane >> 4) & 1) << 3);
    const int b_kof = ((lane >> 3) & 1) << 3;

    #pragma unroll
    for (int ks = 0; ks < 8; ks++) {
        const int k0 = ks << 4;
        uint32_t ah[2][4], al[2][4];
        #pragma unroll
        for (int i = 0; i < 2; i++) {
            uint32_t off = (uint32_t)((a_row + i * 16) * SP + k0 + a_kof) * 2;
            ldsm_x4(ah[i], sAh + off);
            ldsm_x4(al[i], sAl + off);
        }
        uint32_t bh[2][4], bl[2][4];   // [pair16][4 regs: ntile0{k0,k8}, ntile1{k0,k8}]
        #pragma unroll
        for (int p = 0; p < 2; p++) {
            uint32_t off = (uint32_t)((b_n + p * 16) * SP + k0 + b_kof) * 2;
            ldsm_x4(bh[p], sBh + off);
            ldsm_x4(bl[p], sBl + off);
        }
        #pragma unroll
        for (int i = 0; i < 2; i++) {
            #pragma unroll
            for (int j = 0; j < 4; j++) {
                const uint32_t* bfh = &bh[j >> 1][(j & 1) << 1];
                const uint32_t* bfl = &bl[j >> 1][(j & 1) << 1];
                mma16816(acc[i][j], ah[i], bfh);   // hi*hi
                mma16816(acc[i][j], ah[i], bfl);   // hi*lo
                mma16816(acc[i][j], al[i], bfh);   // lo*hi
            }
        }
    }

    // epilogue: lane g=lane>>2 (row within 8), tg=lane&3 (col pair)
    {
        const int g = lane >> 2;
        const int tg = lane & 3;
        #pragma unroll
        for (int i = 0; i < 2; i++) {
            #pragma unroll
            for (int h = 0; h < 2; h++) {
                int r = rowBase + warp_m * 32 + i * 16 + g + h * 8;
                if (r >= M) continue;
                float* o = out0 + (size_t)r * FD;
                if (MODE < 2) {
                    float d = g_dinv[r];
                    #pragma unroll
                    for (int j = 0; j < 4; j++) {
                        int col = warp_n * 32 + j * 8 + tg * 2;
                        float2 v;
                        v.x = acc[i][j][h * 2 + 0] * d;
                        v.y = acc[i][j][h * 2 + 1] * d;
                        *(float2*)(o + col) = v;
                    }
                } else {
                    int gb = batch[r];
                    const float* qp = qc + gb * FD;
                    #pragma unroll
                    for (int j = 0; j < 4; j++) {
                        int col = warp_n * 32 + j * 8 + tg * 2;
                        float2 q = *(const float2*)(qp + col);
                        float2 v;
                        v.x = fmaxf(acc[i][j][h * 2 + 0] + q.x, 0.f);
                        v.y = fmaxf(acc[i][j][h * 2 + 1] + q.y, 0.f);
                        *(float2*)(o + col) = v;
                    }
                }
            }
        }
    }
}

// ---------------- CSR gather: agg[n] = hs[n] + sum_in hs[src] ; 8-way MLP ----------------
__global__ void __launch_bounds__(256)
k_gather(const float* __restrict__ hs, float* __restrict__ agg)
{
    const int warp = (blockIdx.x * blockDim.x + threadIdx.x) >> 5;
    if (warp >= NN) return;
    const int lane = threadIdx.x & 31;

    const float4* hp = (const float4*)hs;
    float4 a0 = hp[(size_t)warp * 32 + lane];
    float4 a1 = make_float4(0.f, 0.f, 0.f, 0.f);
    float4 a2 = make_float4(0.f, 0.f, 0.f, 0.f);
    float4 a3 = make_float4(0.f, 0.f, 0.f, 0.f);

    const int e0 = g_off[warp];
    const int e1 = g_off[warp + 1];
    int i = e0;
    for (; i + 8 <= e1; i += 8) {
        int s0 = g_csr[i],   s1 = g_csr[i+1], s2 = g_csr[i+2], s3 = g_csr[i+3];
        int s4 = g_csr[i+4], s5 = g_csr[i+5], s6 = g_csr[i+6], s7 = g_csr[i+7];
        float4 v0 = hp[(size_t)s0 * 32 + lane];
        float4 v1 = hp[(size_t)s1 * 32 + lane];
        float4 v2 = hp[(size_t)s2 * 32 + lane];
        float4 v3 = hp[(size_t)s3 * 32 + lane];
        float4 v4 = hp[(size_t)s4 * 32 + lane];
        float4 v5 = hp[(size_t)s5 * 32 + lane];
        float4 v6 = hp[(size_t)s6 * 32 + lane];
        float4 v7 = hp[(size_t)s7 * 32 + lane];
        a0.x += v0.x; a0.y += v0.y; a0.z += v0.z; a0.w += v0.w;
        a1.x += v1.x; a1.y += v1.y; a1.z += v1.z; a1.w += v1.w;
        a2.x += v2.x; a2.y += v2.y; a2.z += v2.z; a2.w += v2.w;
        a3.x += v3.x; a3.y += v3.y; a3.z += v3.z; a3.w += v3.w;
        a0.x += v4.x; a0.y += v4.y; a0.z += v4.z; a0.w += v4.w;
        a1.x += v5.x; a1.y += v5.y; a1.z += v5.z; a1.w += v5.w;
        a2.x += v6.x; a2.y += v6.y; a2.z += v6.z; a2.w += v6.w;
        a3.x += v7.x; a3.y += v7.y; a3.z += v7.z; a3.w += v7.w;
    }
    for (; i + 4 <= e1; i += 4) {
        int s0 = g_csr[i], s1 = g_csr[i+1], s2 = g_csr[i+2], s3 = g_csr[i+3];
        float4 v0 = hp[(size_t)s0 * 32 + lane];
        float4 v1 = hp[(size_t)s1 * 32 + lane];
        float4 v2 = hp[(size_t)s2 * 32 + lane];
        float4 v3 = hp[(size_t)s3 * 32 + lane];
        a0.x += v0.x; a0.y += v0.y; a0.z += v0.z; a0.w += v0.w;
        a1.x += v1.x; a1.y += v1.y; a1.z += v1.z; a1.w += v1.w;
        a2.x += v2.x; a2.y += v2.y; a2.z += v2.z; a2.w += v2.w;
        a3.x += v3.x; a3.y += v3.y; a3.z += v3.z; a3.w += v3.w;
    }
    for (; i < e1; i++) {
        int s = g_csr[i];
        float4 v = hp[(size_t)s * 32 + lane];
        a0.x += v.x; a0.y += v.y; a0.z += v.z; a0.w += v.w;
    }
    a0.x += a1.x + a2.x + a3.x;
    a0.y += a1.y + a2.y + a3.y;
    a0.z += a1.z + a2.z + a3.z;
    a0.w += a1.w + a2.w + a3.w;
    ((float4*)agg)[(size_t)warp * 32 + lane] = a0;
}

// ---------------- question head ----------------
__global__ void k_qinit(const float* __restrict__ b) {
    int i = blockIdx.x * blockDim.x + threadIdx.x;
    if (i < NG * FD) g_q[i] = b[i & (FD - 1)];
}
__global__ void __launch_bounds__(128)
k_fc0p(const float* __restrict__ qe, const float* __restrict__ w)
{
    __shared__ float sq[FD];
    const int g = blockIdx.x;
    const int c = blockIdx.y;
    const int t = threadIdx.x;
    const int k0 = c * FD;
    sq[t] = qe[g * QD + k0 + t];
    __syncthreads();
    float acc = 0.f;
    #pragma unroll 8
    for (int k = 0; k < FD; k++)
        acc = fmaf(sq[k], w[(k0 + k) * FD + t], acc);
    atomicAdd(&g_q[g * FD + t], acc);
}
__global__ void k_qc(const float* __restrict__ fc1_w, const float* __restrict__ fc1_b)
{
    __shared__ float sq[FD];
    int g = blockIdx.x, t = threadIdx.x;
    sq[t] = fmaxf(g_q[g * FD + t], 0.f);
    __syncthreads();
    float acc = fc1_b[t];
    for (int k = 0; k < FD; k++) acc = fmaf(sq[k], fc1_w[(FD + k) * FD + t], acc);
    g_qc[g * FD + t] = acc;
}

// ---------------- fc2: [50000,128] -> [50000,32] ----------------
__global__ void __launch_bounds__(256)
k_fc2(const float* __restrict__ h, const float* __restrict__ w,
      const float* __restrict__ b, float* __restrict__ out, int M)
{
    __shared__ float WsT[OD][132];
    __shared__ float sb[OD];
    __shared__ float srow[8][FD];
    int tid = threadIdx.x;
    for (int i = tid; i < FD * OD; i += 256) {
        int k = i >> 5, n = i & 31;
        WsT[n][k] = w[i];
    }
    if (tid < OD) sb[tid] = b[tid];
    __syncthreads();

    int lane = tid & 31, wrp = tid >> 5;
    int wg = blockIdx.x * 8 + wrp;
    int nw = gridDim.x * 8;
    for (int r = wg; r < M; r += nw) {
        float4 rv = *(const float4*)(h + (size_t)r * FD + lane * 4);
        *(float4*)&srow[wrp][lane * 4] = rv;
        __syncwarp();
        float acc = sb[lane];
        #pragma unroll
        for (int k = 0; k < FD; k += 4) {
            float4 x4 = *(const float4*)&srow[wrp][k];
            float4 w4 = *(const float4*)&WsT[lane][k];
            acc = fmaf(x4.x, w4.x, acc);
            acc = fmaf(x4.y, w4.y, acc);
            acc = fmaf(x4.z, w4.z, acc);
            acc = fmaf(x4.w, w4.w, acc);
        }
        out[(size_t)r * OD + lane] = acc;
        __syncwarp();
    }
}

// ---------------- launcher ----------------
extern "C" void kernel_launch(void* const* d_in, const int* in_sizes, int n_in,
                              void* d_out, int out_size)
{
    const float* x     = (const float*)d_in[0];
    const int*   ei    = (const int*)d_in[1];
    const int*   batch = (const int*)d_in[2];
    const float* qe    = (const float*)d_in[3];
    const float* W0    = (const float*)d_in[4];
    const float* b0    = (const float*)d_in[5];
    const float* W1    = (const float*)d_in[6];
    const float* b1    = (const float*)d_in[7];
    const float* W2    = (const float*)d_in[8];
    const float* b2    = (const float*)d_in[9];
    const float* fc0w  = (const float*)d_in[10];
    const float* fc0b  = (const float*)d_in[11];
    const float* fc1w  = (const float*)d_in[12];
    const float* fc1b  = (const float*)d_in[13];
    const float* fc2w  = (const float*)d_in[14];
    const float* fc2b  = (const float*)d_in[15];
    float*       out   = (float*)d_out;

    const int* src = ei;
    const int* dst = ei + EE;

    float *hs, *h2, *qc;
    __nv_bfloat16 *wBhi, *wBlo;
    int* cntp;
    cudaGetSymbolAddress((void**)&hs,   g_hs);
    cudaGetSymbolAddress((void**)&h2,   g_h2);
    cudaGetSymbolAddress((void**)&qc,   g_qc);
    cudaGetSymbolAddress((void**)&wBhi, g_wBhi);
    cudaGetSymbolAddress((void**)&wBlo, g_wBlo);
    cudaGetSymbolAddress((void**)&cntp, g_cnt);

    const int SMEM = (2 * MT + 2 * 128) * SP * 2;   // 104448 B
    cudaFuncSetAttribute(k_mma<0>, cudaFuncAttributeMaxDynamicSharedMemorySize, SMEM);
    cudaFuncSetAttribute(k_mma<1>, cudaFuncAttributeMaxDynamicSharedMemorySize, SMEM);
    cudaFuncSetAttribute(k_mma<2>, cudaFuncAttributeMaxDynamicSharedMemorySize, SMEM);

    const int GB = (NN + MT - 1) / MT;           // 782 tiles
    const int EB = 800;
    const int NB = (NN * 32 + 255) / 256;        // gather: warp per node

    // zero degree counters (memset node, not a kernel launch)
    cudaMemsetAsync(cntp, 0, NN * sizeof(int));

    // k0: weight prep
    {
        dim3 pg(16, 4);
        k_prep<<<pg, 256>>>(W0, W1, W2, fc1w);
    }
    // k1-k2: degree count + scan (dinv)
    k_count<<<EB, 256>>>(dst);
    k_scan<<<1, 1024>>>();
    // k3: conv1 GEMM (profiled slot)
    k_mma<0><<<GB, 256, SMEM>>>(x, nullptr, wBhi + 0 * FD * FD, wBlo + 0 * FD * FD,
                                hs, nullptr, nullptr, NN);
    // k4: CSR placement
    k_place<<<EB, 256>>>(src, dst);
    // k5-k7: question head
    k_qinit<<<(NG * FD + 255) / 256, 256>>>(fc0b);
    {
        dim3 gg(NG, QD / FD);
        k_fc0p<<<gg, 128>>>(qe, fc0w);
    }
    k_qc<<<NG, 128>>>(fc1w, fc1b);
    // conv1 aggregate
    k_gather<<<NB, 256>>>(hs, h2);
    // conv2
    k_mma<1><<<GB, 256, SMEM>>>(h2, b0, wBhi + 1 * FD * FD, wBlo + 1 * FD * FD,
                                hs, nullptr, nullptr, NN);
    k_gather<<<NB, 256>>>(hs, h2);
    // conv3
    k_mma<1><<<GB, 256, SMEM>>>(h2, b1, wBhi + 2 * FD * FD, wBlo + 2 * FD * FD,
                                hs, nullptr, nullptr, NN);
    k_gather<<<NB, 256>>>(hs, h2);
    // fc1 (q-contrib via table)
    k_mma<2><<<GB, 256, SMEM>>>(h2, b2, wBhi + 3 * FD * FD, wBlo + 3 * FD * FD,
                                hs, qc, batch, NN);
    // fc2 -> d_out
    k_fc2<<<1024, 256>>>(hs, fc2w, fc2b, out, NN);
}

// round 15
// speedup vs baseline: 1.0417x; 1.0417x over previous
#include <cuda_runtime.h>
#include <cuda_bf16.h>
#include <cstdint>

#define NN 50000
#define EE 800000
#define NG 64
#define FD 128
#define QD 768
#define OD 32

// ---------------- scratch (no allocations allowed) ----------------
__device__ float g_dinv[NN];
__device__ float g_hs  [(size_t)NN * FD];
__device__ float g_h2  [(size_t)NN * FD];
__device__ float g_q [NG * FD];
__device__ float g_qc[NG * FD];
__device__ int   g_cnt[NN];
__device__ int   g_off[NN + 1];
__device__ int   g_cur[NN];
__device__ int   g_csr[EE];
// bf16 weight tiles, [n][k] row-major (col-major B operand): 4 matrices x (hi,lo)
__device__ __nv_bfloat16 g_wBhi[4 * FD * FD];
__device__ __nv_bfloat16 g_wBlo[4 * FD * FD];

__device__ __forceinline__ uint32_t smem_u32(const void* p) {
    uint32_t a;
    asm("{ .reg .u64 t; cvta.to.shared.u64 t, %1; cvt.u32.u64 %0, t; }" : "=r"(a) : "l"(p));
    return a;
}
__device__ __forceinline__ void ldsm_x4(uint32_t* r, uint32_t addr) {
    asm volatile("ldmatrix.sync.aligned.m8n8.x4.shared.b16 {%0,%1,%2,%3}, [%4];"
                 : "=r"(r[0]), "=r"(r[1]), "=r"(r[2]), "=r"(r[3]) : "r"(addr));
}
__device__ __forceinline__ void mma16816(float* c, const uint32_t* a, const uint32_t* b) {
    asm volatile(
        "mma.sync.aligned.m16n8k16.row.col.f32.bf16.bf16.f32 "
        "{%0,%1,%2,%3}, {%4,%5,%6,%7}, {%8,%9}, {%0,%1,%2,%3};"
        : "+f"(c[0]), "+f"(c[1]), "+f"(c[2]), "+f"(c[3])
        : "r"(a[0]), "r"(a[1]), "r"(a[2]), "r"(a[3]), "r"(b[0]), "r"(b[1]));
}

// ---------------- CSR build ----------------
__global__ void k_count(const int* __restrict__ dst) {
    int i = blockIdx.x * blockDim.x + threadIdx.x;
    int stride = gridDim.x * blockDim.x;
    for (; i < EE; i += stride) atomicAdd(&g_cnt[dst[i]], 1);
}
__global__ void __launch_bounds__(1024) k_scan() {
    __shared__ int ps[1024];
    const int t = threadIdx.x;
    const int CH = (NN + 1023) / 1024;
    int b = t * CH, e = b + CH; if (e > NN) e = NN;
    int s = 0;
    for (int i = b; i < e; i++) s += g_cnt[i];
    ps[t] = s;
    __syncthreads();
    for (int d = 1; d < 1024; d <<= 1) {
        int v = (t >= d) ? ps[t - d] : 0;
        __syncthreads();
        ps[t] += v;
        __syncthreads();
    }
    int run = (t > 0) ? ps[t - 1] : 0;
    for (int i = b; i < e; i++) {
        g_off[i] = run;
        g_cur[i] = run;
        g_dinv[i] = rsqrtf((float)(g_cnt[i] + 1));
        run += g_cnt[i];
    }
    if (t == 1023) g_off[NN] = run;
}
__global__ void k_place(const int* __restrict__ src, const int* __restrict__ dst) {
    int i = blockIdx.x * blockDim.x + threadIdx.x;
    int stride = gridDim.x * blockDim.x;
    for (; i < EE; i += stride) {
        int d = dst[i];
        int p = atomicAdd(&g_cur[d], 1);
        g_csr[p] = src[i];
    }
}

// ---------------- weight prep: W[k][n] fp32 -> B[n][k] split bf16 ----------------
__global__ void k_prep(const float* __restrict__ W0, const float* __restrict__ W1,
                       const float* __restrict__ W2, const float* __restrict__ F1)
{
    const float* Ws[4] = {W0, W1, W2, F1};
    int mat = blockIdx.y;
    const float* W = Ws[mat];
    __nv_bfloat16* bh = g_wBhi + mat * FD * FD;
    __nv_bfloat16* bl = g_wBlo + mat * FD * FD;
    for (int idx = blockIdx.x * blockDim.x + threadIdx.x; idx < FD * FD;
         idx += gridDim.x * blockDim.x) {
        int k = idx >> 7, n = idx & 127;
        float v = W[idx];
        __nv_bfloat16 hi = __float2bfloat16_rn(v);
        __nv_bfloat16 lo = __float2bfloat16_rn(v - __bfloat162float(hi));
        bh[n * FD + k] = hi;
        bl[n * FD + k] = lo;
    }
}

// ---------------- tensor-core GEMM: [M,128] x [128,128], split-bf16 3-term ----------------
// 512 threads, 16 warps in 4x4 grid, warp tile 32x32. (R12 config — best measured)
// MODE 0: plain A load; epilogue raw store (dinv moved to gather)
// MODE 1: A load = relu(dinv*a + bias_in); epilogue raw store
// MODE 2: A load = relu(dinv*a + bias_in); epilogue relu(acc + qc[batch[row]])
#define SP 136   // padded smem row stride in bf16 elems (272B: odd 16B units -> ldsm conflict-free)
template<int MODE>
__global__ void __launch_bounds__(512, 1)
k_mma(const float* __restrict__ A, const float* __restrict__ bias_in,
      const __nv_bfloat16* __restrict__ Bhi, const __nv_bfloat16* __restrict__ Blo,
      float* __restrict__ out0,
      const float* __restrict__ qc, const int* __restrict__ batch, int M)
{
    extern __shared__ __align__(16) __nv_bfloat16 sm[];
    __nv_bfloat16* Ah = sm;
    __nv_bfloat16* Al = sm + 128 * SP;
    __nv_bfloat16* Bh = sm + 2 * 128 * SP;
    __nv_bfloat16* Bl = sm + 3 * 128 * SP;

    const int tid = threadIdx.x;
    const int wid = tid >> 5;
    const int lane = tid & 31;
    const int rowBase = blockIdx.x << 7;

    // copy B tiles (16384 bf16 each)
    for (int i = tid; i < 2048; i += 512) {
        int n = i >> 4;
        int k = (i & 15) << 3;
        uint4 vh = ((const uint4*)Bhi)[i];
        uint4 vl = ((const uint4*)Blo)[i];
        *(uint4*)&Bh[n * SP + k] = vh;
        *(uint4*)&Bl[n * SP + k] = vl;
    }
    // load (+optional transform) + split A
    for (int f = tid; f < 4096; f += 512) {
        int row = f >> 5;
        int col = (f & 31) << 2;
        int r = rowBase + row;
        float4 v = make_float4(0.f, 0.f, 0.f, 0.f);
        if (r < M) v = *(const float4*)(A + (size_t)r * FD + col);
        if (MODE != 0) {
            float dv = (r < M) ? g_dinv[r] : 0.f;
            float4 bb = *(const float4*)(bias_in + col);
            v.x = fmaxf(fmaf(dv, v.x, bb.x), 0.f);
            v.y = fmaxf(fmaf(dv, v.y, bb.y), 0.f);
            v.z = fmaxf(fmaf(dv, v.z, bb.z), 0.f);
            v.w = fmaxf(fmaf(dv, v.w, bb.w), 0.f);
        }
        __nv_bfloat16 hx = __float2bfloat16_rn(v.x);
        __nv_bfloat16 hy = __float2bfloat16_rn(v.y);
        __nv_bfloat16 hz = __float2bfloat16_rn(v.z);
        __nv_bfloat16 hw = __float2bfloat16_rn(v.w);
        __nv_bfloat162 h01, h23, l01, l23;
        h01.x = hx; h01.y = hy; h23.x = hz; h23.y = hw;
        l01.x = __float2bfloat16_rn(v.x - __bfloat162float(hx));
        l01.y = __float2bfloat16_rn(v.y - __bfloat162float(hy));
        l23.x = __float2bfloat16_rn(v.z - __bfloat162float(hz));
        l23.y = __float2bfloat16_rn(v.w - __bfloat162float(hw));
        uint2 hv, lv;
        hv.x = *(uint32_t*)&h01; hv.y = *(uint32_t*)&h23;
        lv.x = *(uint32_t*)&l01; lv.y = *(uint32_t*)&l23;
        *(uint2*)&Ah[row * SP + col] = hv;
        *(uint2*)&Al[row * SP + col] = lv;
    }
    __syncthreads();

    const int warp_m = wid & 3;       // rows 32*warp_m
    const int warp_n = wid >> 2;      // cols 32*warp_n

    float acc[2][4][4];
    #pragma unroll
    for (int i = 0; i < 2; i++)
        #pragma unroll
        for (int j = 0; j < 4; j++)
            #pragma unroll
            for (int q = 0; q < 4; q++) acc[i][j][q] = 0.f;

    const uint32_t sAh = smem_u32(Ah);
    const uint32_t sAl = smem_u32(Al);
    const uint32_t sBh = smem_u32(Bh);
    const uint32_t sBl = smem_u32(Bl);

    const int a_row = warp_m * 32 + (lane & 15);
    const int a_kof = (lane >> 4) << 3;
    const int b_n   = warp_n * 32 + (lane & 7) + (((lane >> 4) & 1) << 3);
    const int b_kof = ((lane >> 3) & 1) << 3;

    #pragma unroll
    for (int ks = 0; ks < 8; ks++) {
        const int k0 = ks << 4;
        uint32_t ah[2][4], al[2][4];
        #pragma unroll
        for (int i = 0; i < 2; i++) {
            uint32_t off = (uint32_t)((a_row + i * 16) * SP + k0 + a_kof) * 2;
            ldsm_x4(ah[i], sAh + off);
            ldsm_x4(al[i], sAl + off);
        }
        uint32_t bh[2][4], bl[2][4];
        #pragma unroll
        for (int p = 0; p < 2; p++) {
            uint32_t off = (uint32_t)((b_n + p * 16) * SP + k0 + b_kof) * 2;
            ldsm_x4(bh[p], sBh + off);
            ldsm_x4(bl[p], sBl + off);
        }
        #pragma unroll
        for (int i = 0; i < 2; i++) {
            #pragma unroll
            for (int j = 0; j < 4; j++) {
                const uint32_t* bfh = &bh[j >> 1][(j & 1) << 1];
                const uint32_t* bfl = &bl[j >> 1][(j & 1) << 1];
                mma16816(acc[i][j], ah[i], bfh);   // hi*hi
                mma16816(acc[i][j], ah[i], bfl);   // hi*lo
                mma16816(acc[i][j], al[i], bfh);   // lo*hi
            }
        }
    }

    // epilogue: lane g=lane>>2 (row within 8), tg=lane&3 (col pair)
    {
        const int g = lane >> 2;
        const int tg = lane & 3;
        #pragma unroll
        for (int i = 0; i < 2; i++) {
            #pragma unroll
            for (int h = 0; h < 2; h++) {
                int r = rowBase + warp_m * 32 + i * 16 + g + h * 8;
                if (r >= M) continue;
                float* o = out0 + (size_t)r * FD;
                if (MODE < 2) {
                    #pragma unroll
                    for (int j = 0; j < 4; j++) {
                        int col = warp_n * 32 + j * 8 + tg * 2;
                        float2 v;
                        v.x = acc[i][j][h * 2 + 0];
                        v.y = acc[i][j][h * 2 + 1];
                        *(float2*)(o + col) = v;
                    }
                } else {
                    int gb = batch[r];
                    const float* qp = qc + gb * FD;
                    #pragma unroll
                    for (int j = 0; j < 4; j++) {
                        int col = warp_n * 32 + j * 8 + tg * 2;
                        float2 q = *(const float2*)(qp + col);
                        float2 v;
                        v.x = fmaxf(acc[i][j][h * 2 + 0] + q.x, 0.f);
                        v.y = fmaxf(acc[i][j][h * 2 + 1] + q.y, 0.f);
                        *(float2*)(o + col) = v;
                    }
                }
            }
        }
    }
}

// ---------------- CSR gather with dinv: agg[n] = dinv[n]*p[n] + sum_in dinv[s]*p[s] ----------------
__global__ void __launch_bounds__(256)
k_gather(const float* __restrict__ hs, float* __restrict__ agg)
{
    const int warp = (blockIdx.x * blockDim.x + threadIdx.x) >> 5;
    if (warp >= NN) return;
    const int lane = threadIdx.x & 31;

    const float4* hp = (const float4*)hs;
    float dn = __ldg(g_dinv + warp);
    float4 sv = hp[(size_t)warp * 32 + lane];
    float4 a0, a1, a2, a3;
    a0.x = dn * sv.x; a0.y = dn * sv.y; a0.z = dn * sv.z; a0.w = dn * sv.w;
    a1 = make_float4(0.f, 0.f, 0.f, 0.f);
    a2 = make_float4(0.f, 0.f, 0.f, 0.f);
    a3 = make_float4(0.f, 0.f, 0.f, 0.f);

    const int e0 = g_off[warp];
    const int e1 = g_off[warp + 1];
    int i = e0;
    for (; i + 8 <= e1; i += 8) {
        int s0 = g_csr[i],   s1 = g_csr[i+1], s2 = g_csr[i+2], s3 = g_csr[i+3];
        int s4 = g_csr[i+4], s5 = g_csr[i+5], s6 = g_csr[i+6], s7 = g_csr[i+7];
        float d0 = __ldg(g_dinv + s0), d1 = __ldg(g_dinv + s1);
        float d2 = __ldg(g_dinv + s2), d3 = __ldg(g_dinv + s3);
        float d4 = __ldg(g_dinv + s4), d5 = __ldg(g_dinv + s5);
        float d6 = __ldg(g_dinv + s6), d7 = __ldg(g_dinv + s7);
        float4 v0 = hp[(size_t)s0 * 32 + lane];
        float4 v1 = hp[(size_t)s1 * 32 + lane];
        float4 v2 = hp[(size_t)s2 * 32 + lane];
        float4 v3 = hp[(size_t)s3 * 32 + lane];
        float4 v4 = hp[(size_t)s4 * 32 + lane];
        float4 v5 = hp[(size_t)s5 * 32 + lane];
        float4 v6 = hp[(size_t)s6 * 32 + lane];
        float4 v7 = hp[(size_t)s7 * 32 + lane];
        a0.x = fmaf(d0, v0.x, a0.x); a0.y = fmaf(d0, v0.y, a0.y); a0.z = fmaf(d0, v0.z, a0.z); a0.w = fmaf(d0, v0.w, a0.w);
        a1.x = fmaf(d1, v1.x, a1.x); a1.y = fmaf(d1, v1.y, a1.y); a1.z = fmaf(d1, v1.z, a1.z); a1.w = fmaf(d1, v1.w, a1.w);
        a2.x = fmaf(d2, v2.x, a2.x); a2.y = fmaf(d2, v2.y, a2.y); a2.z = fmaf(d2, v2.z, a2.z); a2.w = fmaf(d2, v2.w, a2.w);
        a3.x = fmaf(d3, v3.x, a3.x); a3.y = fmaf(d3, v3.y, a3.y); a3.z = fmaf(d3, v3.z, a3.z); a3.w = fmaf(d3, v3.w, a3.w);
        a0.x = fmaf(d4, v4.x, a0.x); a0.y = fmaf(d4, v4.y, a0.y); a0.z = fmaf(d4, v4.z, a0.z); a0.w = fmaf(d4, v4.w, a0.w);
        a1.x = fmaf(d5, v5.x, a1.x); a1.y = fmaf(d5, v5.y, a1.y); a1.z = fmaf(d5, v5.z, a1.z); a1.w = fmaf(d5, v5.w, a1.w);
        a2.x = fmaf(d6, v6.x, a2.x); a2.y = fmaf(d6, v6.y, a2.y); a2.z = fmaf(d6, v6.z, a2.z); a2.w = fmaf(d6, v6.w, a2.w);
        a3.x = fmaf(d7, v7.x, a3.x); a3.y = fmaf(d7, v7.y, a3.y); a3.z = fmaf(d7, v7.z, a3.z); a3.w = fmaf(d7, v7.w, a3.w);
    }
    for (; i < e1; i++) {
        int s = g_csr[i];
        float ds = __ldg(g_dinv + s);
        float4 v = hp[(size_t)s * 32 + lane];
        a0.x = fmaf(ds, v.x, a0.x); a0.y = fmaf(ds, v.y, a0.y);
        a0.z = fmaf(ds, v.z, a0.z); a0.w = fmaf(ds, v.w, a0.w);
    }
    a0.x += a1.x + a2.x + a3.x;
    a0.y += a1.y + a2.y + a3.y;
    a0.z += a1.z + a2.z + a3.z;
    a0.w += a1.w + a2.w + a3.w;
    ((float4*)agg)[(size_t)warp * 32 + lane] = a0;
}

// ---------------- question head ----------------
__global__ void k_qinit(const float* __restrict__ b) {
    int i = blockIdx.x * blockDim.x + threadIdx.x;
    if (i < NG * FD) g_q[i] = b[i & (FD - 1)];
}
__global__ void __launch_bounds__(128)
k_fc0p(const float* __restrict__ qe, const float* __restrict__ w)
{
    __shared__ float sq[FD];
    const int g = blockIdx.x;
    const int c = blockIdx.y;
    const int t = threadIdx.x;
    const int k0 = c * FD;
    sq[t] = qe[g * QD + k0 + t];
    __syncthreads();
    float acc = 0.f;
    #pragma unroll 8
    for (int k = 0; k < FD; k++)
        acc = fmaf(sq[k], w[(k0 + k) * FD + t], acc);
    atomicAdd(&g_q[g * FD + t], acc);
}
__global__ void k_qc(const float* __restrict__ fc1_w, const float* __restrict__ fc1_b)
{
    __shared__ float sq[FD];
    int g = blockIdx.x, t = threadIdx.x;
    sq[t] = fmaxf(g_q[g * FD + t], 0.f);
    __syncthreads();
    float acc = fc1_b[t];
    for (int k = 0; k < FD; k++) acc = fmaf(sq[k], fc1_w[(FD + k) * FD + t], acc);
    g_qc[g * FD + t] = acc;
}

// ---------------- fc2: [50000,128] -> [50000,32] ----------------
__global__ void __launch_bounds__(256)
k_fc2(const float* __restrict__ h, const float* __restrict__ w,
      const float* __restrict__ b, float* __restrict__ out, int M)
{
    __shared__ float WsT[OD][132];
    __shared__ float sb[OD];
    __shared__ float srow[8][FD];
    int tid = threadIdx.x;
    for (int i = tid; i < FD * OD; i += 256) {
        int k = i >> 5, n = i & 31;
        WsT[n][k] = w[i];
    }
    if (tid < OD) sb[tid] = b[tid];
    __syncthreads();

    int lane = tid & 31, wrp = tid >> 5;
    int wg = blockIdx.x * 8 + wrp;
    int nw = gridDim.x * 8;
    for (int r = wg; r < M; r += nw) {
        float4 rv = *(const float4*)(h + (size_t)r * FD + lane * 4);
        *(float4*)&srow[wrp][lane * 4] = rv;
        __syncwarp();
        float acc = sb[lane];
        #pragma unroll
        for (int k = 0; k < FD; k += 4) {
            float4 x4 = *(const float4*)&srow[wrp][k];
            float4 w4 = *(const float4*)&WsT[lane][k];
            acc = fmaf(x4.x, w4.x, acc);
            acc = fmaf(x4.y, w4.y, acc);
            acc = fmaf(x4.z, w4.z, acc);
            acc = fmaf(x4.w, w4.w, acc);
        }
        out[(size_t)r * OD + lane] = acc;
        __syncwarp();
    }
}

// ---------------- launcher ----------------
extern "C" void kernel_launch(void* const* d_in, const int* in_sizes, int n_in,
                              void* d_out, int out_size)
{
    const float* x     = (const float*)d_in[0];
    const int*   ei    = (const int*)d_in[1];
    const int*   batch = (const int*)d_in[2];
    const float* qe    = (const float*)d_in[3];
    const float* W0    = (const float*)d_in[4];
    const float* b0    = (const float*)d_in[5];
    const float* W1    = (const float*)d_in[6];
    const float* b1    = (const float*)d_in[7];
    const float* W2    = (const float*)d_in[8];
    const float* b2    = (const float*)d_in[9];
    const float* fc0w  = (const float*)d_in[10];
    const float* fc0b  = (const float*)d_in[11];
    const float* fc1w  = (const float*)d_in[12];
    const float* fc1b  = (const float*)d_in[13];
    const float* fc2w  = (const float*)d_in[14];
    const float* fc2b  = (const float*)d_in[15];
    float*       out   = (float*)d_out;

    const int* src = ei;
    const int* dst = ei + EE;

    float *hs, *h2, *qc;
    __nv_bfloat16 *wBhi, *wBlo;
    int* cntp;
    cudaGetSymbolAddress((void**)&hs,   g_hs);
    cudaGetSymbolAddress((void**)&h2,   g_h2);
    cudaGetSymbolAddress((void**)&qc,   g_qc);
    cudaGetSymbolAddress((void**)&wBhi, g_wBhi);
    cudaGetSymbolAddress((void**)&wBlo, g_wBlo);
    cudaGetSymbolAddress((void**)&cntp, g_cnt);

    const int SMEM = 4 * 128 * SP * 2;            // 139264 B
    cudaFuncSetAttribute(k_mma<0>, cudaFuncAttributeMaxDynamicSharedMemorySize, SMEM);
    cudaFuncSetAttribute(k_mma<1>, cudaFuncAttributeMaxDynamicSharedMemorySize, SMEM);
    cudaFuncSetAttribute(k_mma<2>, cudaFuncAttributeMaxDynamicSharedMemorySize, SMEM);

    // one-time stream/event creation on the correctness (non-captured) call;
    // capture calls reuse the handles via capture-legal record/wait.
    static cudaStream_t s1 = nullptr;
    static cudaEvent_t  e0 = nullptr, e1 = nullptr;
    if (s1 == nullptr) {
        cudaStreamCreateWithFlags(&s1, cudaStreamNonBlocking);
        cudaEventCreateWithFlags(&e0, cudaEventDisableTiming);
        cudaEventCreateWithFlags(&e1, cudaEventDisableTiming);
    }

    const int GB = (NN + 127) / 128;             // 391 tiles
    const int EB = 800;
    const int NB = (NN * 32 + 255) / 256;        // gather: warp per node

    // ---- fork: side chain (CSR build + question head) on s1 ----
    cudaEventRecord(e0, 0);
    cudaStreamWaitEvent(s1, e0, 0);
    cudaMemsetAsync(cntp, 0, NN * sizeof(int), s1);
    k_count<<<EB, 256, 0, s1>>>(dst);
    k_scan<<<1, 1024, 0, s1>>>();
    k_place<<<EB, 256, 0, s1>>>(src, dst);
    k_qinit<<<(NG * FD + 255) / 256, 256, 0, s1>>>(fc0b);
    {
        dim3 gg(NG, QD / FD);
        k_fc0p<<<gg, 128, 0, s1>>>(qe, fc0w);
    }
    k_qc<<<NG, 128, 0, s1>>>(fc1w, fc1b);
    cudaEventRecord(e1, s1);

    // ---- main chain: prep + conv1 GEMM (no dinv dependency now) ----
    {
        dim3 pg(16, 4);
        k_prep<<<pg, 256>>>(W0, W1, W2, fc1w);
    }
    k_mma<0><<<GB, 512, SMEM>>>(x, nullptr, wBhi + 0 * FD * FD, wBlo + 0 * FD * FD,
                                hs, nullptr, nullptr, NN);

    // ---- join: gathers need CSR + dinv ----
    cudaStreamWaitEvent(0, e1, 0);
    k_gather<<<NB, 256>>>(hs, h2);
    // conv2
    k_mma<1><<<GB, 512, SMEM>>>(h2, b0, wBhi + 1 * FD * FD, wBlo + 1 * FD * FD,
                                hs, nullptr, nullptr, NN);
    k_gather<<<NB, 256>>>(hs, h2);
    // conv3
    k_mma<1><<<GB, 512, SMEM>>>(h2, b1, wBhi + 2 * FD * FD, wBlo + 2 * FD * FD,
                                hs, nullptr, nullptr, NN);
    k_gather<<<NB, 256>>>(hs, h2);
    // fc1 (q-contrib via table)
    k_mma<2><<<GB, 512, SMEM>>>(h2, b2, wBhi + 3 * FD * FD, wBlo + 3 * FD * FD,
                                hs, qc, batch, NN);
    // fc2 -> d_out
    k_fc2<<<1024, 256>>>(hs, fc2w, fc2b, out, NN);
}

// round 17
// speedup vs baseline: 1.0744x; 1.0314x over previous
#include <cuda_runtime.h>
#include <cuda_bf16.h>
#include <cstdint>

#define NN 50000
#define EE 800000
#define NG 64
#define FD 128
#define QD 768
#define OD 32

// ---------------- scratch (no allocations allowed) ----------------
__device__ float g_dinv[NN];
__device__ float g_hs  [(size_t)NN * FD];
__device__ float g_h2  [(size_t)NN * FD];
__device__ float g_q [NG * FD];
__device__ float g_qc[NG * FD];
__device__ int   g_cnt[NN];
__device__ int   g_off[NN + 1];
__device__ int   g_cur[NN];
__device__ int   g_csr[EE];
// bf16 weight tiles, [n][k] row-major (col-major B operand): 4 matrices x (hi,lo)
__device__ __nv_bfloat16 g_wBhi[4 * FD * FD];
__device__ __nv_bfloat16 g_wBlo[4 * FD * FD];

__device__ __forceinline__ uint32_t smem_u32(const void* p) {
    uint32_t a;
    asm("{ .reg .u64 t; cvta.to.shared.u64 t, %1; cvt.u32.u64 %0, t; }" : "=r"(a) : "l"(p));
    return a;
}
__device__ __forceinline__ void ldsm_x4(uint32_t* r, uint32_t addr) {
    asm volatile("ldmatrix.sync.aligned.m8n8.x4.shared.b16 {%0,%1,%2,%3}, [%4];"
                 : "=r"(r[0]), "=r"(r[1]), "=r"(r[2]), "=r"(r[3]) : "r"(addr));
}
__device__ __forceinline__ void mma16816(float* c, const uint32_t* a, const uint32_t* b) {
    asm volatile(
        "mma.sync.aligned.m16n8k16.row.col.f32.bf16.bf16.f32 "
        "{%0,%1,%2,%3}, {%4,%5,%6,%7}, {%8,%9}, {%0,%1,%2,%3};"
        : "+f"(c[0]), "+f"(c[1]), "+f"(c[2]), "+f"(c[3])
        : "r"(a[0]), "r"(a[1]), "r"(a[2]), "r"(a[3]), "r"(b[0]), "r"(b[1]));
}

// ---------------- CSR build ----------------
__global__ void k_count(const int* __restrict__ dst) {
    int i = blockIdx.x * blockDim.x + threadIdx.x;
    int stride = gridDim.x * blockDim.x;
    for (; i < EE; i += stride) atomicAdd(&g_cnt[dst[i]], 1);
}
__global__ void __launch_bounds__(1024) k_scan() {
    __shared__ int ps[1024];
    const int t = threadIdx.x;
    const int CH = (NN + 1023) / 1024;
    int b = t * CH, e = b + CH; if (e > NN) e = NN;
    int s = 0;
    for (int i = b; i < e; i++) s += g_cnt[i];
    ps[t] = s;
    __syncthreads();
    for (int d = 1; d < 1024; d <<= 1) {
        int v = (t >= d) ? ps[t - d] : 0;
        __syncthreads();
        ps[t] += v;
        __syncthreads();
    }
    int run = (t > 0) ? ps[t - 1] : 0;
    for (int i = b; i < e; i++) {
        g_off[i] = run;
        g_cur[i] = run;
        g_dinv[i] = rsqrtf((float)(g_cnt[i] + 1));
        run += g_cnt[i];
    }
    if (t == 1023) g_off[NN] = run;
}
__global__ void k_place(const int* __restrict__ src, const int* __restrict__ dst) {
    int i = blockIdx.x * blockDim.x + threadIdx.x;
    int stride = gridDim.x * blockDim.x;
    for (; i < EE; i += stride) {
        int d = dst[i];
        int p = atomicAdd(&g_cur[d], 1);
        g_csr[p] = src[i];
    }
}

// ---------------- weight prep: W[k][n] fp32 -> B[n][k] split bf16 ----------------
__global__ void k_prep(const float* __restrict__ W0, const float* __restrict__ W1,
                       const float* __restrict__ W2, const float* __restrict__ F1)
{
    const float* Ws[4] = {W0, W1, W2, F1};
    int mat = blockIdx.y;
    const float* W = Ws[mat];
    __nv_bfloat16* bh = g_wBhi + mat * FD * FD;
    __nv_bfloat16* bl = g_wBlo + mat * FD * FD;
    for (int idx = blockIdx.x * blockDim.x + threadIdx.x; idx < FD * FD;
         idx += gridDim.x * blockDim.x) {
        int k = idx >> 7, n = idx & 127;
        float v = W[idx];
        __nv_bfloat16 hi = __float2bfloat16_rn(v);
        __nv_bfloat16 lo = __float2bfloat16_rn(v - __bfloat162float(hi));
        bh[n * FD + k] = hi;
        bl[n * FD + k] = lo;
    }
}

// ---------------- tensor-core GEMM: [M,128] x [128,128], split-bf16 3-term ----------------
// 1024 threads, 32 warps in 8(m) x 4(n) grid, warp tile 16x32. Regs capped at 64.
// MODE 0: plain A load; epilogue raw store (dinv applied in gather)
// MODE 1: A load = relu(dinv*a + bias_in); epilogue raw store
// MODE 2: A load = relu(dinv*a + bias_in); epilogue relu(acc + qc[batch[row]])
#define SP 136   // padded smem row stride in bf16 elems (272B: odd 16B units -> ldsm conflict-free)
template<int MODE>
__global__ void __launch_bounds__(1024, 1)
k_mma(const float* __restrict__ A, const float* __restrict__ bias_in,
      const __nv_bfloat16* __restrict__ Bhi, const __nv_bfloat16* __restrict__ Blo,
      float* __restrict__ out0,
      const float* __restrict__ qc, const int* __restrict__ batch, int M)
{
    extern __shared__ __align__(16) __nv_bfloat16 sm[];
    __nv_bfloat16* Ah = sm;
    __nv_bfloat16* Al = sm + 128 * SP;
    __nv_bfloat16* Bh = sm + 2 * 128 * SP;
    __nv_bfloat16* Bl = sm + 3 * 128 * SP;

    const int tid = threadIdx.x;
    const int wid = tid >> 5;
    const int lane = tid & 31;
    const int rowBase = blockIdx.x << 7;

    // copy B tiles (16384 bf16 each): 2048 uint4 pairs over 1024 threads
    for (int i = tid; i < 2048; i += 1024) {
        int n = i >> 4;
        int k = (i & 15) << 3;
        uint4 vh = ((const uint4*)Bhi)[i];
        uint4 vl = ((const uint4*)Blo)[i];
        *(uint4*)&Bh[n * SP + k] = vh;
        *(uint4*)&Bl[n * SP + k] = vl;
    }
    // load (+optional transform) + split A
    for (int f = tid; f < 4096; f += 1024) {
        int row = f >> 5;
        int col = (f & 31) << 2;
        int r = rowBase + row;
        float4 v = make_float4(0.f, 0.f, 0.f, 0.f);
        if (r < M) v = *(const float4*)(A + (size_t)r * FD + col);
        if (MODE != 0) {
            float dv = (r < M) ? g_dinv[r] : 0.f;
            float4 bb = *(const float4*)(bias_in + col);
            v.x = fmaxf(fmaf(dv, v.x, bb.x), 0.f);
            v.y = fmaxf(fmaf(dv, v.y, bb.y), 0.f);
            v.z = fmaxf(fmaf(dv, v.z, bb.z), 0.f);
            v.w = fmaxf(fmaf(dv, v.w, bb.w), 0.f);
        }
        __nv_bfloat16 hx = __float2bfloat16_rn(v.x);
        __nv_bfloat16 hy = __float2bfloat16_rn(v.y);
        __nv_bfloat16 hz = __float2bfloat16_rn(v.z);
        __nv_bfloat16 hw = __float2bfloat16_rn(v.w);
        __nv_bfloat162 h01, h23, l01, l23;
        h01.x = hx; h01.y = hy; h23.x = hz; h23.y = hw;
        l01.x = __float2bfloat16_rn(v.x - __bfloat162float(hx));
        l01.y = __float2bfloat16_rn(v.y - __bfloat162float(hy));
        l23.x = __float2bfloat16_rn(v.z - __bfloat162float(hz));
        l23.y = __float2bfloat16_rn(v.w - __bfloat162float(hw));
        uint2 hv, lv;
        hv.x = *(uint32_t*)&h01; hv.y = *(uint32_t*)&h23;
        lv.x = *(uint32_t*)&l01; lv.y = *(uint32_t*)&l23;
        *(uint2*)&Ah[row * SP + col] = hv;
        *(uint2*)&Al[row * SP + col] = lv;
    }
    __syncthreads();

    const int warp_m = wid & 7;       // rows 16*warp_m
    const int warp_n = wid >> 3;      // cols 32*warp_n

    float acc[4][4];
    #pragma unroll
    for (int j = 0; j < 4; j++)
        #pragma unroll
        for (int q = 0; q < 4; q++) acc[j][q] = 0.f;

    const uint32_t sAh = smem_u32(Ah);
    const uint32_t sAl = smem_u32(Al);
    const uint32_t sBh = smem_u32(Bh);
    const uint32_t sBl = smem_u32(Bl);

    const int a_row = warp_m * 16 + (lane & 15);
    const int a_kof = (lane >> 4) << 3;
    const int b_n   = warp_n * 32 + (lane & 7) + (((lane >> 4) & 1) << 3);
    const int b_kof = ((lane >> 3) & 1) << 3;

    #pragma unroll
    for (int ks = 0; ks < 8; ks++) {
        const int k0 = ks << 4;
        uint32_t ah[4], al[4];
        {
            uint32_t off = (uint32_t)(a_row * SP + k0 + a_kof) * 2;
            ldsm_x4(ah, sAh + off);
            ldsm_x4(al, sAl + off);
        }
        uint32_t bh[2][4], bl[2][4];   // [pair16][4 regs: ntile0{k0,k8}, ntile1{k0,k8}]
        #pragma unroll
        for (int p = 0; p < 2; p++) {
            uint32_t off = (uint32_t)((b_n + p * 16) * SP + k0 + b_kof) * 2;
            ldsm_x4(bh[p], sBh + off);
            ldsm_x4(bl[p], sBl + off);
        }
        #pragma unroll
        for (int j = 0; j < 4; j++) {
            const uint32_t* bfh = &bh[j >> 1][(j & 1) << 1];
            const uint32_t* bfl = &bl[j >> 1][(j & 1) << 1];
            mma16816(acc[j], ah, bfh);   // hi*hi
            mma16816(acc[j], ah, bfl);   // hi*lo
            mma16816(acc[j], al, bfh);   // lo*hi
        }
    }

    // epilogue: lane g=lane>>2 (row within 8), tg=lane&3 (col pair)
    {
        const int g = lane >> 2;
        const int tg = lane & 3;
        #pragma unroll
        for (int h = 0; h < 2; h++) {
            int r = rowBase + warp_m * 16 + g + h * 8;
            if (r >= M) continue;
            float* o = out0 + (size_t)r * FD;
            if (MODE < 2) {
                #pragma unroll
                for (int j = 0; j < 4; j++) {
                    int col = warp_n * 32 + j * 8 + tg * 2;
                    float2 v;
                    v.x = acc[j][h * 2 + 0];
                    v.y = acc[j][h * 2 + 1];
                    *(float2*)(o + col) = v;
                }
            } else {
                int gb = batch[r];
                const float* qp = qc + gb * FD;
                #pragma unroll
                for (int j = 0; j < 4; j++) {
                    int col = warp_n * 32 + j * 8 + tg * 2;
                    float2 q = *(const float2*)(qp + col);
                    float2 v;
                    v.x = fmaxf(acc[j][h * 2 + 0] + q.x, 0.f);
                    v.y = fmaxf(acc[j][h * 2 + 1] + q.y, 0.f);
                    *(float2*)(o + col) = v;
                }
            }
        }
    }
}

// ---------------- CSR gather with dinv: agg[n] = dinv[n]*p[n] + sum_in dinv[s]*p[s] ----------------
__global__ void __launch_bounds__(256)
k_gather(const float* __restrict__ hs, float* __restrict__ agg)
{
    const int warp = (blockIdx.x * blockDim.x + threadIdx.x) >> 5;
    if (warp >= NN) return;
    const int lane = threadIdx.x & 31;

    const float4* hp = (const float4*)hs;
    float dn = __ldg(g_dinv + warp);
    float4 sv = hp[(size_t)warp * 32 + lane];
    float4 a0, a1, a2, a3;
    a0.x = dn * sv.x; a0.y = dn * sv.y; a0.z = dn * sv.z; a0.w = dn * sv.w;
    a1 = make_float4(0.f, 0.f, 0.f, 0.f);
    a2 = make_float4(0.f, 0.f, 0.f, 0.f);
    a3 = make_float4(0.f, 0.f, 0.f, 0.f);

    const int e0 = g_off[warp];
    const int e1 = g_off[warp + 1];
    int i = e0;
    for (; i + 8 <= e1; i += 8) {
        int s0 = g_csr[i],   s1 = g_csr[i+1], s2 = g_csr[i+2], s3 = g_csr[i+3];
        int s4 = g_csr[i+4], s5 = g_csr[i+5], s6 = g_csr[i+6], s7 = g_csr[i+7];
        float d0 = __ldg(g_dinv + s0), d1 = __ldg(g_dinv + s1);
        float d2 = __ldg(g_dinv + s2), d3 = __ldg(g_dinv + s3);
        float d4 = __ldg(g_dinv + s4), d5 = __ldg(g_dinv + s5);
        float d6 = __ldg(g_dinv + s6), d7 = __ldg(g_dinv + s7);
        float4 v0 = hp[(size_t)s0 * 32 + lane];
        float4 v1 = hp[(size_t)s1 * 32 + lane];
        float4 v2 = hp[(size_t)s2 * 32 + lane];
        float4 v3 = hp[(size_t)s3 * 32 + lane];
        float4 v4 = hp[(size_t)s4 * 32 + lane];
        float4 v5 = hp[(size_t)s5 * 32 + lane];
        float4 v6 = hp[(size_t)s6 * 32 + lane];
        float4 v7 = hp[(size_t)s7 * 32 + lane];
        a0.x = fmaf(d0, v0.x, a0.x); a0.y = fmaf(d0, v0.y, a0.y); a0.z = fmaf(d0, v0.z, a0.z); a0.w = fmaf(d0, v0.w, a0.w);
        a1.x = fmaf(d1, v1.x, a1.x); a1.y = fmaf(d1, v1.y, a1.y); a1.z = fmaf(d1, v1.z, a1.z); a1.w = fmaf(d1, v1.w, a1.w);
        a2.x = fmaf(d2, v2.x, a2.x); a2.y = fmaf(d2, v2.y, a2.y); a2.z = fmaf(d2, v2.z, a2.z); a2.w = fmaf(d2, v2.w, a2.w);
        a3.x = fmaf(d3, v3.x, a3.x); a3.y = fmaf(d3, v3.y, a3.y); a3.z = fmaf(d3, v3.z, a3.z); a3.w = fmaf(d3, v3.w, a3.w);
        a0.x = fmaf(d4, v4.x, a0.x); a0.y = fmaf(d4, v4.y, a0.y); a0.z = fmaf(d4, v4.z, a0.z); a0.w = fmaf(d4, v4.w, a0.w);
        a1.x = fmaf(d5, v5.x, a1.x); a1.y = fmaf(d5, v5.y, a1.y); a1.z = fmaf(d5, v5.z, a1.z); a1.w = fmaf(d5, v5.w, a1.w);
        a2.x = fmaf(d6, v6.x, a2.x); a2.y = fmaf(d6, v6.y, a2.y); a2.z = fmaf(d6, v6.z, a2.z); a2.w = fmaf(d6, v6.w, a2.w);
        a3.x = fmaf(d7, v7.x, a3.x); a3.y = fmaf(d7, v7.y, a3.y); a3.z = fmaf(d7, v7.z, a3.z); a3.w = fmaf(d7, v7.w, a3.w);
    }
    for (; i < e1; i++) {
        int s = g_csr[i];
        float ds = __ldg(g_dinv + s);
        float4 v = hp[(size_t)s * 32 + lane];
        a0.x = fmaf(ds, v.x, a0.x); a0.y = fmaf(ds, v.y, a0.y);
        a0.z = fmaf(ds, v.z, a0.z); a0.w = fmaf(ds, v.w, a0.w);
    }
    a0.x += a1.x + a2.x + a3.x;
    a0.y += a1.y + a2.y + a3.y;
    a0.z += a1.z + a2.z + a3.z;
    a0.w += a1.w + a2.w + a3.w;
    ((float4*)agg)[(size_t)warp * 32 + lane] = a0;
}

// ---------------- question head ----------------
__global__ void k_qinit(const float* __restrict__ b) {
    int i = blockIdx.x * blockDim.x + threadIdx.x;
    if (i < NG * FD) g_q[i] = b[i & (FD - 1)];
}
__global__ void __launch_bounds__(128)
k_fc0p(const float* __restrict__ qe, const float* __restrict__ w)
{
    __shared__ float sq[FD];
    const int g = blockIdx.x;
    const int c = blockIdx.y;
    const int t = threadIdx.x;
    const int k0 = c * FD;
    sq[t] = qe[g * QD + k0 + t];
    __syncthreads();
    float acc = 0.f;
    #pragma unroll 8
    for (int k = 0; k < FD; k++)
        acc = fmaf(sq[k], w[(k0 + k) * FD + t], acc);
    atomicAdd(&g_q[g * FD + t], acc);
}
__global__ void k_qc(const float* __restrict__ fc1_w, const float* __restrict__ fc1_b)
{
    __shared__ float sq[FD];
    int g = blockIdx.x, t = threadIdx.x;
    sq[t] = fmaxf(g_q[g * FD + t], 0.f);
    __syncthreads();
    float acc = fc1_b[t];
    for (int k = 0; k < FD; k++) acc = fmaf(sq[k], fc1_w[(FD + k) * FD + t], acc);
    g_qc[g * FD + t] = acc;
}

// ---------------- fc2: [50000,128] -> [50000,32] ----------------
__global__ void __launch_bounds__(256)
k_fc2(const float* __restrict__ h, const float* __restrict__ w,
      const float* __restrict__ b, float* __restrict__ out, int M)
{
    __shared__ float WsT[OD][132];
    __shared__ float sb[OD];
    __shared__ float srow[8][FD];
    int tid = threadIdx.x;
    for (int i = tid; i < FD * OD; i += 256) {
        int k = i >> 5, n = i & 31;
        WsT[n][k] = w[i];
    }
    if (tid < OD) sb[tid] = b[tid];
    __syncthreads();

    int lane = tid & 31, wrp = tid >> 5;
    int wg = blockIdx.x * 8 + wrp;
    int nw = gridDim.x * 8;
    for (int r = wg; r < M; r += nw) {
        float4 rv = *(const float4*)(h + (size_t)r * FD + lane * 4);
        *(float4*)&srow[wrp][lane * 4] = rv;
        __syncwarp();
        float acc = sb[lane];
        #pragma unroll
        for (int k = 0; k < FD; k += 4) {
            float4 x4 = *(const float4*)&srow[wrp][k];
            float4 w4 = *(const float4*)&WsT[lane][k];
            acc = fmaf(x4.x, w4.x, acc);
            acc = fmaf(x4.y, w4.y, acc);
            acc = fmaf(x4.z, w4.z, acc);
            acc = fmaf(x4.w, w4.w, acc);
        }
        out[(size_t)r * OD + lane] = acc;
        __syncwarp();
    }
}

// ---------------- launcher ----------------
extern "C" void kernel_launch(void* const* d_in, const int* in_sizes, int n_in,
                              void* d_out, int out_size)
{
    const float* x     = (const float*)d_in[0];
    const int*   ei    = (const int*)d_in[1];
    const int*   batch = (const int*)d_in[2];
    const float* qe    = (const float*)d_in[3];
    const float* W0    = (const float*)d_in[4];
    const float* b0    = (const float*)d_in[5];
    const float* W1    = (const float*)d_in[6];
    const float* b1    = (const float*)d_in[7];
    const float* W2    = (const float*)d_in[8];
    const float* b2    = (const float*)d_in[9];
    const float* fc0w  = (const float*)d_in[10];
    const float* fc0b  = (const float*)d_in[11];
    const float* fc1w  = (const float*)d_in[12];
    const float* fc1b  = (const float*)d_in[13];
    const float* fc2w  = (const float*)d_in[14];
    const float* fc2b  = (const float*)d_in[15];
    float*       out   = (float*)d_out;

    const int* src = ei;
    const int* dst = ei + EE;

    float *hs, *h2, *qc;
    __nv_bfloat16 *wBhi, *wBlo;
    int* cntp;
    cudaGetSymbolAddress((void**)&hs,   g_hs);
    cudaGetSymbolAddress((void**)&h2,   g_h2);
    cudaGetSymbolAddress((void**)&qc,   g_qc);
    cudaGetSymbolAddress((void**)&wBhi, g_wBhi);
    cudaGetSymbolAddress((void**)&wBlo, g_wBlo);
    cudaGetSymbolAddress((void**)&cntp, g_cnt);

    const int SMEM = 4 * 128 * SP * 2;            // 139264 B
    cudaFuncSetAttribute(k_mma<0>, cudaFuncAttributeMaxDynamicSharedMemorySize, SMEM);
    cudaFuncSetAttribute(k_mma<1>, cudaFuncAttributeMaxDynamicSharedMemorySize, SMEM);
    cudaFuncSetAttribute(k_mma<2>, cudaFuncAttributeMaxDynamicSharedMemorySize, SMEM);

    // one-time stream/event creation on the correctness (non-captured) call;
    // capture calls reuse the handles via capture-legal record/wait.
    static cudaStream_t s1 = nullptr;
    static cudaEvent_t  e0 = nullptr, e1 = nullptr;
    if (s1 == nullptr) {
        cudaStreamCreateWithFlags(&s1, cudaStreamNonBlocking);
        cudaEventCreateWithFlags(&e0, cudaEventDisableTiming);
        cudaEventCreateWithFlags(&e1, cudaEventDisableTiming);
    }

    const int GB = (NN + 127) / 128;             // 391 tiles
    const int EB = 800;
    const int NB = (NN * 32 + 255) / 256;        // gather: warp per node

    // ---- fork: side chain (CSR build + question head) on s1 ----
    cudaEventRecord(e0, 0);
    cudaStreamWaitEvent(s1, e0, 0);
    cudaMemsetAsync(cntp, 0, NN * sizeof(int), s1);
    k_count<<<EB, 256, 0, s1>>>(dst);
    k_scan<<<1, 1024, 0, s1>>>();
    k_place<<<EB, 256, 0, s1>>>(src, dst);
    k_qinit<<<(NG * FD + 255) / 256, 256, 0, s1>>>(fc0b);
    {
        dim3 gg(NG, QD / FD);
        k_fc0p<<<gg, 128, 0, s1>>>(qe, fc0w);
    }
    k_qc<<<NG, 128, 0, s1>>>(fc1w, fc1b);
    cudaEventRecord(e1, s1);

    // ---- main chain: prep + conv1 GEMM (no dinv dependency) ----
    {
        dim3 pg(16, 4);
        k_prep<<<pg, 256>>>(W0, W1, W2, fc1w);
    }
    k_mma<0><<<GB, 1024, SMEM>>>(x, nullptr, wBhi + 0 * FD * FD, wBlo + 0 * FD * FD,
                                 hs, nullptr, nullptr, NN);

    // ---- join: gathers need CSR + dinv ----
    cudaStreamWaitEvent(0, e1, 0);
    k_gather<<<NB, 256>>>(hs, h2);
    // conv2
    k_mma<1><<<GB, 1024, SMEM>>>(h2, b0, wBhi + 1 * FD * FD, wBlo + 1 * FD * FD,
                                 hs, nullptr, nullptr, NN);
    k_gather<<<NB, 256>>>(hs, h2);
    // conv3
    k_mma<1><<<GB, 1024, SMEM>>>(h2, b1, wBhi + 2 * FD * FD, wBlo + 2 * FD * FD,
                                 hs, nullptr, nullptr, NN);
    k_gather<<<NB, 256>>>(hs, h2);
    // fc1 (q-contrib via table)
    k_mma<2><<<GB, 1024, SMEM>>>(h2, b2, wBhi + 3 * FD * FD, wBlo + 3 * FD * FD,
                                 hs, qc, batch, NN);
    // fc2 -> d_out
    k_fc2<<<1024, 256>>>(hs, fc2w, fc2b, out, NN);
}